// round 1
// baseline (speedup 1.0000x reference)
#include <cuda_runtime.h>
#include <cstdint>

// Problem constants (fixed by the dataset)
#define HID   256      // HIDDEN
#define FEA   192      // OUT_EMB
#define NMAX  50000    // num nodes
#define NB    64       // nodes per block in node kernel
#define NT    256      // threads per block (node kernel)
#define KC    16       // K-chunk for W staging
#define TSTR  66       // padded transposed-row stride (floats)

typedef unsigned long long ull;

// Scratch: scatter-add destination [N, HID]. 51.2 MB, L2-resident.
__device__ float g_xn[(size_t)NMAX * HID];
__device__ int   g_idx_is64;

// ---------------------------------------------------------------------------
// Packed f32x2 FMA (Blackwell; only reachable via PTX per SASS_QUICKREF)
// ---------------------------------------------------------------------------
__device__ __forceinline__ ull fma2(ull a, ull b, ull c) {
    ull d;
    asm("fma.rn.f32x2 %0, %1, %2, %3;" : "=l"(d) : "l"(a), "l"(b), "l"(c));
    return d;
}

// ---------------------------------------------------------------------------
// Kernel 0: detect whether index tensor is int64 (high words all zero) or int32
// ---------------------------------------------------------------------------
__global__ void detect_idx_kernel(const unsigned int* __restrict__ w, int E) {
    if (blockIdx.x == 0 && threadIdx.x == 0) {
        int n = E < 512 ? E : 512;
        int ok = 1;
        for (int k = 0; k < n; k++)
            if (w[2 * k + 1] != 0u) { ok = 0; break; }
        g_idx_is64 = ok;
    }
}

// ---------------------------------------------------------------------------
// Kernel 1: zero the scatter buffer
// ---------------------------------------------------------------------------
__global__ void zero_xn_kernel(int n4) {
    float4* p = reinterpret_cast<float4*>(g_xn);
    const float4 z = make_float4(0.f, 0.f, 0.f, 0.f);
    for (int i = blockIdx.x * blockDim.x + threadIdx.x; i < n4;
         i += gridDim.x * blockDim.x)
        p[i] = z;
}

// ---------------------------------------------------------------------------
// Kernel 2: fused edge stage.
// Each 64-thread group owns one edge per iteration; thread q handles channels
// [4q, 4q+4). W_rbf columns live in registers across the grid-stride loop.
// g = rbf[e,:] @ W_rbf ; xe = g * x[e,:] ; red.v4 into g_xn[i[e],:].
// ---------------------------------------------------------------------------
__global__ __launch_bounds__(256) void edge_kernel(
    const float* __restrict__ x, const float* __restrict__ rbf,
    const void* __restrict__ idx, const float* __restrict__ W_rbf, int E)
{
    const int tid = threadIdx.x;
    const int q   = tid & 63;
    const int eo  = tid >> 6;

    float4 w[6];
#pragma unroll
    for (int r = 0; r < 6; r++)
        w[r] = *reinterpret_cast<const float4*>(W_rbf + r * HID + q * 4);

    const int is64 = g_idx_is64;
    const long long estep = (long long)gridDim.x * 4;

    for (long long e = (long long)blockIdx.x * 4 + eo; e < E; e += estep) {
        const float* rb = rbf + e * 6;
        float r0 = rb[0], r1 = rb[1], r2 = rb[2];
        float r3 = rb[3], r4 = rb[4], r5 = rb[5];

        int node = is64 ? (int)reinterpret_cast<const long long*>(idx)[e]
                        : reinterpret_cast<const int*>(idx)[e];

        float4 xv = *reinterpret_cast<const float4*>(x + e * HID + q * 4);

        float4 g;
        g.x = r0*w[0].x + r1*w[1].x + r2*w[2].x + r3*w[3].x + r4*w[4].x + r5*w[5].x;
        g.y = r0*w[0].y + r1*w[1].y + r2*w[2].y + r3*w[3].y + r4*w[4].y + r5*w[5].y;
        g.z = r0*w[0].z + r1*w[1].z + r2*w[2].z + r3*w[3].z + r4*w[4].z + r5*w[5].z;
        g.w = r0*w[0].w + r1*w[1].w + r2*w[2].w + r3*w[3].w + r4*w[4].w + r5*w[5].w;

        float v0 = g.x * xv.x, v1 = g.y * xv.y, v2 = g.z * xv.z, v3 = g.w * xv.w;

        float* p = g_xn + (size_t)node * HID + q * 4;
        asm volatile("red.global.add.v4.f32 [%0], {%1, %2, %3, %4};"
                     :: "l"(p), "f"(v0), "f"(v1), "f"(v2), "f"(v3) : "memory");
    }
}

// ---------------------------------------------------------------------------
// Node MLP: fused GEMM chain, all intermediates in shared memory.
// Input tile stored TRANSPOSED ([K][TSTR], node index contiguous) so
// node-pairs are contiguous LDS.64 for f32x2 packing.
// W chunk staged DUPLICATED ({w,w} per column) so the broadcast multiplier is
// a single LDS.64 — no pack MOVs in the inner loop.
// Thread micro-tile: 8 nodes (4 f32x2 pairs) x 6 columns (tc, tc+32, ... tc+160).
// ---------------------------------------------------------------------------
template<int K, bool ACT>
__device__ __forceinline__ void run_layer(
    const float* __restrict__ Wg, const float* __restrict__ bias,
    const float* __restrict__ inT, float* __restrict__ outT,
    float* __restrict__ sW2, int tid)
{
    const int tc = tid & 31;        // column base (cols tc + 32m)
    const int tn = tid >> 5;        // node group: nodes [8*tn, 8*tn+8)
    const int n0 = tn * 8;

    ull acc[4][6];
#pragma unroll
    for (int i = 0; i < 4; i++)
#pragma unroll
        for (int j = 0; j < 6; j++) acc[i][j] = 0ULL;

    for (int k0 = 0; k0 < K; k0 += KC) {
        // stage duplicated W chunk: sW2[kk][c] = {W[k0+kk][c], W[k0+kk][c]}
        for (int t = tid; t < KC * FEA; t += NT) {
            int kk = t / FEA;
            int c  = t - kk * FEA;
            float v = Wg[(k0 + kk) * FEA + c];
            reinterpret_cast<float2*>(sW2)[kk * FEA + c] = make_float2(v, v);
        }
        __syncthreads();

#pragma unroll
        for (int kk = 0; kk < KC; kk++) {
            const float* ar = inT + (k0 + kk) * TSTR + n0;
            ull a0 = *reinterpret_cast<const ull*>(ar);
            ull a1 = *reinterpret_cast<const ull*>(ar + 2);
            ull a2 = *reinterpret_cast<const ull*>(ar + 4);
            ull a3 = *reinterpret_cast<const ull*>(ar + 6);
            const ull* wr = reinterpret_cast<const ull*>(sW2) + kk * FEA + tc;
#pragma unroll
            for (int j = 0; j < 6; j++) {
                ull wj = wr[32 * j];
                acc[0][j] = fma2(a0, wj, acc[0][j]);
                acc[1][j] = fma2(a1, wj, acc[1][j]);
                acc[2][j] = fma2(a2, wj, acc[2][j]);
                acc[3][j] = fma2(a3, wj, acc[3][j]);
            }
        }
        __syncthreads();
    }

    // epilogue: bias (+ SiLU), write transposed into outT
#pragma unroll
    for (int j = 0; j < 6; j++) {
        const int c = tc + 32 * j;
        const float b = bias[c];
#pragma unroll
        for (int i = 0; i < 4; i++) {
            float2 v = *reinterpret_cast<float2*>(&acc[i][j]);
            float v0 = v.x + b, v1 = v.y + b;
            if (ACT) {
                v0 = v0 / (1.f + __expf(-v0));
                v1 = v1 / (1.f + __expf(-v1));
            }
            *reinterpret_cast<float2*>(outT + c * TSTR + n0 + 2 * i) =
                make_float2(v0, v1);
        }
    }
    __syncthreads();
}

__global__ __launch_bounds__(NT, 1) void node_kernel(
    const float* __restrict__ W_up,  const float* __restrict__ b_up,
    const float* __restrict__ W_lins, const float* __restrict__ b_lins,
    const float* __restrict__ W_out, float* __restrict__ out, int N)
{
    extern __shared__ float sm[];
    float* sT0  = sm;                          // [HID][TSTR]  (67.6 KB)
    float* sT1  = sT0 + HID * TSTR;            // [FEA][TSTR]  (50.7 KB)
    float* sW2  = sT1 + FEA * TSTR;            // [KC][2*FEA]  (24.6 KB)
    float* sRed = sW2 + KC * 2 * FEA;          // [4][64]

    const int tid   = threadIdx.x;
    const int node0 = blockIdx.x * NB;

    // load xn tile, transposed: sT0[k][n] = xn[node0+n][k]
    for (int t = tid; t < NB * HID; t += NT) {
        int k = t & (HID - 1);
        int n = t >> 8;
        int node = node0 + n;
        sT0[k * TSTR + n] = (node < N) ? g_xn[(size_t)node * HID + k] : 0.f;
    }
    __syncthreads();

    run_layer<HID, false>(W_up, b_up, sT0, sT1, sW2, tid);
    run_layer<FEA, true >(W_lins + 0 * FEA * FEA, b_lins + 0 * FEA, sT1, sT0, sW2, tid);
    run_layer<FEA, true >(W_lins + 1 * FEA * FEA, b_lins + 1 * FEA, sT0, sT1, sW2, tid);
    run_layer<FEA, true >(W_lins + 2 * FEA * FEA, b_lins + 2 * FEA, sT1, sT0, sW2, tid);

    // final projection FEA -> 1 (h lives transposed in sT0)
    const int n    = tid & 63;
    const int part = tid >> 6;
    float s = 0.f;
#pragma unroll
    for (int c = part * 48; c < part * 48 + 48; c++)
        s += sT0[c * TSTR + n] * W_out[c];
    sRed[part * 64 + n] = s;
    __syncthreads();
    if (tid < 64) {
        int node = node0 + tid;
        if (node < N)
            out[node] = sRed[tid] + sRed[64 + tid] + sRed[128 + tid] + sRed[192 + tid];
    }
}

// ---------------------------------------------------------------------------
// launch
// ---------------------------------------------------------------------------
extern "C" void kernel_launch(void* const* d_in, const int* in_sizes, int n_in,
                              void* d_out, int out_size)
{
    const float* x    = (const float*)d_in[0];
    const float* rbf  = (const float*)d_in[1];
    const void*  idx  = d_in[2];
    // num_nodes scalar may or may not be materialized as an input
    const int wo = (n_in >= 10) ? 4 : 3;
    const float* W_rbf  = (const float*)d_in[wo + 0];
    const float* W_up   = (const float*)d_in[wo + 1];
    const float* b_up   = (const float*)d_in[wo + 2];
    const float* W_lins = (const float*)d_in[wo + 3];
    const float* b_lins = (const float*)d_in[wo + 4];
    const float* W_out  = (const float*)d_in[wo + 5];

    const int E = in_sizes[0] / HID;
    const int N = out_size;   // OUT == 1

    const size_t smem =
        (size_t)(HID * TSTR + FEA * TSTR + KC * 2 * FEA + 256) * sizeof(float);
    cudaFuncSetAttribute(node_kernel,
                         cudaFuncAttributeMaxDynamicSharedMemorySize, (int)smem);

    detect_idx_kernel<<<1, 32>>>((const unsigned int*)idx, E);
    zero_xn_kernel<<<2048, 256>>>(N * HID / 4);
    edge_kernel<<<2048, 256>>>(x, rbf, idx, W_rbf, E);
    node_kernel<<<(N + NB - 1) / NB, NT, smem>>>(W_up, b_up, W_lins, b_lins,
                                                 W_out, (float*)d_out, N);
}

// round 3
// speedup vs baseline: 1.3310x; 1.3310x over previous
#include <cuda_runtime.h>
#include <cuda_bf16.h>
#include <cstdint>

#define HID 256
#define FEA 192
#define NMAX 50000
#define MB 128          // nodes per block (node kernel)
#define NT 256          // threads per block (node kernel)

#define ACT_STR 264     // act row stride in floats (16B aligned, conflict-tuned)
#define BSTR 40         // sB row stride in halfs

// smem layout (bytes)
#define SM_BH   (MB * ACT_STR * 4)            // 135168
#define SM_BL   (SM_BH + FEA * BSTR * 2)      // +15360
#define SM_BIAS (SM_BL + FEA * BSTR * 2)      // +15360
#define SM_TOT  (SM_BIAS + 5 * FEA * 4)       // +3840 = 169728

__device__ float g_xn[(size_t)NMAX * HID];
__device__ int   g_idx_is64;

// ---------------------------------------------------------------------------
// helpers
// ---------------------------------------------------------------------------
__device__ __forceinline__ void split1(float v, uint16_t& h, uint16_t& l) {
    __nv_bfloat16 hb = __float2bfloat16(v);
    float r = v - __bfloat162float(hb);
    __nv_bfloat16 lb = __float2bfloat16(r);
    h = __bfloat16_as_ushort(hb);
    l = __bfloat16_as_ushort(lb);
}

__device__ __forceinline__ void split2(float a, float b, uint32_t& hw, uint32_t& lw) {
    uint16_t ha, la, hb, lb;
    split1(a, ha, la);
    split1(b, hb, lb);
    hw = ((uint32_t)hb << 16) | ha;
    lw = ((uint32_t)lb << 16) | la;
}

__device__ __forceinline__ void mma_bf16(float* d,
                                         uint32_t a0, uint32_t a1, uint32_t a2, uint32_t a3,
                                         uint32_t b0, uint32_t b1) {
    asm volatile(
        "mma.sync.aligned.m16n8k16.row.col.f32.bf16.bf16.f32 "
        "{%0,%1,%2,%3}, {%4,%5,%6,%7}, {%8,%9}, {%0,%1,%2,%3};"
        : "+f"(d[0]), "+f"(d[1]), "+f"(d[2]), "+f"(d[3])
        : "r"(a0), "r"(a1), "r"(a2), "r"(a3), "r"(b0), "r"(b1));
}

// ---------------------------------------------------------------------------
// edge stage
// ---------------------------------------------------------------------------
__global__ void detect_idx_kernel(const unsigned int* __restrict__ w, int E) {
    __shared__ int bad;
    if (threadIdx.x == 0) bad = 0;
    __syncthreads();
    int n = E < 512 ? E : 512;
    for (int k = threadIdx.x; k < n; k += blockDim.x)
        if (w[2 * k + 1] != 0u) bad = 1;
    __syncthreads();
    if (threadIdx.x == 0) g_idx_is64 = !bad;
}

__global__ void zero_xn_kernel(int n4) {
    float4* p = reinterpret_cast<float4*>(g_xn);
    const float4 z = make_float4(0.f, 0.f, 0.f, 0.f);
    for (int i = blockIdx.x * blockDim.x + threadIdx.x; i < n4;
         i += gridDim.x * blockDim.x)
        p[i] = z;
}

__global__ __launch_bounds__(256) void edge_kernel(
    const float* __restrict__ x, const float* __restrict__ rbf,
    const void* __restrict__ idx, const float* __restrict__ W_rbf, int E)
{
    const int tid = threadIdx.x;
    const int q   = tid & 63;
    const int eo  = tid >> 6;

    float4 w[6];
#pragma unroll
    for (int r = 0; r < 6; r++)
        w[r] = *reinterpret_cast<const float4*>(W_rbf + r * HID + q * 4);

    const int is64 = g_idx_is64;
    const long long estep = (long long)gridDim.x * 4;

    for (long long e = (long long)blockIdx.x * 4 + eo; e < E; e += estep) {
        const float* rb = rbf + e * 6;
        float r0 = rb[0], r1 = rb[1], r2 = rb[2];
        float r3 = rb[3], r4 = rb[4], r5 = rb[5];

        int node = is64 ? (int)reinterpret_cast<const long long*>(idx)[e]
                        : reinterpret_cast<const int*>(idx)[e];

        float4 xv = *reinterpret_cast<const float4*>(x + e * HID + q * 4);

        float4 g;
        g.x = r0*w[0].x + r1*w[1].x + r2*w[2].x + r3*w[3].x + r4*w[4].x + r5*w[5].x;
        g.y = r0*w[0].y + r1*w[1].y + r2*w[2].y + r3*w[3].y + r4*w[4].y + r5*w[5].y;
        g.z = r0*w[0].z + r1*w[1].z + r2*w[2].z + r3*w[3].z + r4*w[4].z + r5*w[5].z;
        g.w = r0*w[0].w + r1*w[1].w + r2*w[2].w + r3*w[3].w + r4*w[4].w + r5*w[5].w;

        float v0 = g.x * xv.x, v1 = g.y * xv.y, v2 = g.z * xv.z, v3 = g.w * xv.w;

        float* p = g_xn + (size_t)node * HID + q * 4;
        asm volatile("red.global.add.v4.f32 [%0], {%1, %2, %3, %4};"
                     :: "l"(p), "f"(v0), "f"(v1), "f"(v2), "f"(v3) : "memory");
    }
}

// ---------------------------------------------------------------------------
// node MLP: mma.sync bf16 3-term split-precision GEMM chain
// ---------------------------------------------------------------------------
template<int K, bool ACT>
__device__ __forceinline__ void layer(
    const float* __restrict__ Wg, const float* __restrict__ bias,
    float* __restrict__ act, uint16_t* __restrict__ sBh, uint16_t* __restrict__ sBl,
    int tid, int lane, int warp_m, int warp_n)
{
    const int g = lane >> 2;
    const int q = lane & 3;

    float d[2][12][4];
#pragma unroll
    for (int tm = 0; tm < 2; tm++)
#pragma unroll
        for (int j = 0; j < 12; j++)
#pragma unroll
            for (int u = 0; u < 4; u++) d[tm][j][u] = 0.f;

    for (int k0 = 0; k0 < K; k0 += 32) {
        __syncthreads();
        // stage weight chunk [32][192] -> bf16 hi/lo in [n][BSTR]
        for (int t = tid; t < 32 * FEA; t += NT) {
            int kk = t / FEA;
            int n  = t - kk * FEA;
            float v = Wg[(k0 + kk) * FEA + n];
            uint16_t h, l;
            split1(v, h, l);
            sBh[n * BSTR + kk] = h;
            sBl[n * BSTR + kk] = l;
        }
        __syncthreads();

#pragma unroll
        for (int ks = 0; ks < 32; ks += 16) {
            // A fragments (fp32 -> bf16 hi/lo)
            uint32_t ah[2][4], al[2][4];
#pragma unroll
            for (int tm = 0; tm < 2; tm++) {
                int r0 = warp_m * 32 + tm * 16 + g;
                const float* p0 = act + r0 * ACT_STR + k0 + ks + q * 2;
                const float* p1 = act + (r0 + 8) * ACT_STR + k0 + ks + q * 2;
                float2 v0 = *(const float2*)p0;
                float2 v1 = *(const float2*)p1;
                float2 v2 = *(const float2*)(p0 + 8);
                float2 v3 = *(const float2*)(p1 + 8);
                split2(v0.x, v0.y, ah[tm][0], al[tm][0]);
                split2(v1.x, v1.y, ah[tm][1], al[tm][1]);
                split2(v2.x, v2.y, ah[tm][2], al[tm][2]);
                split2(v3.x, v3.y, ah[tm][3], al[tm][3]);
            }
#pragma unroll
            for (int j = 0; j < 12; j++) {
                int n = warp_n * 96 + j * 8 + g;
                const uint32_t* bh = reinterpret_cast<const uint32_t*>(sBh) + (n * BSTR + ks) / 2;
                const uint32_t* bl = reinterpret_cast<const uint32_t*>(sBl) + (n * BSTR + ks) / 2;
                uint32_t bh0 = bh[q], bh1 = bh[q + 4];
                uint32_t bl0 = bl[q], bl1 = bl[q + 4];
#pragma unroll
                for (int tm = 0; tm < 2; tm++) {
                    mma_bf16(d[tm][j], ah[tm][0], ah[tm][1], ah[tm][2], ah[tm][3], bh0, bh1);
                    mma_bf16(d[tm][j], al[tm][0], al[tm][1], al[tm][2], al[tm][3], bh0, bh1);
                    mma_bf16(d[tm][j], ah[tm][0], ah[tm][1], ah[tm][2], ah[tm][3], bl0, bl1);
                }
            }
        }
    }
    __syncthreads();
    // epilogue: bias (+silu), write back into act (input fully consumed)
#pragma unroll
    for (int tm = 0; tm < 2; tm++) {
        int r0 = warp_m * 32 + tm * 16 + g;
#pragma unroll
        for (int j = 0; j < 12; j++) {
            int c = warp_n * 96 + j * 8 + q * 2;
            float b0 = bias[c], b1 = bias[c + 1];
            float x0 = d[tm][j][0] + b0, x1 = d[tm][j][1] + b1;
            float x2 = d[tm][j][2] + b0, x3 = d[tm][j][3] + b1;
            if (ACT) {
                x0 = x0 / (1.f + __expf(-x0));
                x1 = x1 / (1.f + __expf(-x1));
                x2 = x2 / (1.f + __expf(-x2));
                x3 = x3 / (1.f + __expf(-x3));
            }
            *(float2*)(act + r0 * ACT_STR + c)       = make_float2(x0, x1);
            *(float2*)(act + (r0 + 8) * ACT_STR + c) = make_float2(x2, x3);
        }
    }
    __syncthreads();
}

__global__ __launch_bounds__(NT, 1) void node_kernel(
    const float* __restrict__ W_up,  const float* __restrict__ b_up,
    const float* __restrict__ W_lins, const float* __restrict__ b_lins,
    const float* __restrict__ W_out, float* __restrict__ out, int N)
{
    extern __shared__ char smem[];
    float*    act   = reinterpret_cast<float*>(smem);
    uint16_t* sBh   = reinterpret_cast<uint16_t*>(smem + SM_BH);
    uint16_t* sBl   = reinterpret_cast<uint16_t*>(smem + SM_BL);
    float*    sBias = reinterpret_cast<float*>(smem + SM_BIAS);

    const int tid = threadIdx.x;
    const int lane = tid & 31, warp = tid >> 5;
    const int warp_m = warp & 3, warp_n = warp >> 2;
    const int node0 = blockIdx.x * MB;

    for (int t = tid; t < FEA; t += NT) {
        sBias[t]           = b_up[t];
        sBias[FEA + t]     = b_lins[t];
        sBias[2 * FEA + t] = b_lins[FEA + t];
        sBias[3 * FEA + t] = b_lins[2 * FEA + t];
        sBias[4 * FEA + t] = W_out[t];
    }
    // load xn tile [128][256]
    for (int t = tid; t < MB * HID / 4; t += NT) {
        int row = t >> 6;
        int c4  = t & 63;
        int node = node0 + row;
        float4 v = (node < N)
            ? reinterpret_cast<const float4*>(g_xn + (size_t)node * HID)[c4]
            : make_float4(0.f, 0.f, 0.f, 0.f);
        *(float4*)(act + row * ACT_STR + c4 * 4) = v;
    }
    __syncthreads();

    layer<HID, false>(W_up,                  sBias,           act, sBh, sBl, tid, lane, warp_m, warp_n);
    layer<FEA, true >(W_lins,                sBias + FEA,     act, sBh, sBl, tid, lane, warp_m, warp_n);
    layer<FEA, true >(W_lins + FEA * FEA,    sBias + 2 * FEA, act, sBh, sBl, tid, lane, warp_m, warp_n);
    layer<FEA, true >(W_lins + 2 * FEA * FEA,sBias + 3 * FEA, act, sBh, sBl, tid, lane, warp_m, warp_n);

    // final projection FEA -> 1
    {
        const int node = tid >> 1, half = tid & 1;
        const float4* hrow = reinterpret_cast<const float4*>(act + node * ACT_STR + half * 96);
        const float4* w    = reinterpret_cast<const float4*>(sBias + 4 * FEA + half * 96);
        float s = 0.f;
#pragma unroll
        for (int c = 0; c < 24; c++) {
            float4 a = hrow[c], b = w[c];
            s += a.x * b.x + a.y * b.y + a.z * b.z + a.w * b.w;
        }
        s += __shfl_xor_sync(0xffffffffu, s, 1);
        if (half == 0 && node0 + node < N) out[node0 + node] = s;
    }
}

// ---------------------------------------------------------------------------
// launch
// ---------------------------------------------------------------------------
extern "C" void kernel_launch(void* const* d_in, const int* in_sizes, int n_in,
                              void* d_out, int out_size)
{
    const float* x    = (const float*)d_in[0];
    const float* rbf  = (const float*)d_in[1];
    const void*  idx  = d_in[2];
    const int wo = (n_in >= 10) ? 4 : 3;
    const float* W_rbf  = (const float*)d_in[wo + 0];
    const float* W_up   = (const float*)d_in[wo + 1];
    const float* b_up   = (const float*)d_in[wo + 2];
    const float* W_lins = (const float*)d_in[wo + 3];
    const float* b_lins = (const float*)d_in[wo + 4];
    const float* W_out  = (const float*)d_in[wo + 5];

    const int E = in_sizes[0] / HID;
    const int N = out_size;

    cudaFuncSetAttribute(node_kernel,
                         cudaFuncAttributeMaxDynamicSharedMemorySize, SM_TOT);

    detect_idx_kernel<<<1, 256>>>((const unsigned int*)idx, E);
    zero_xn_kernel<<<2048, 256>>>(N * HID / 4);
    edge_kernel<<<2048, 256>>>(x, rbf, idx, W_rbf, E);
    node_kernel<<<(N + MB - 1) / MB, NT, SM_TOT>>>(
        W_up, b_up, W_lins, b_lins, W_out, (float*)d_out, N);
}

// round 4
// speedup vs baseline: 1.9728x; 1.4822x over previous
#include <cuda_runtime.h>
#include <cuda_bf16.h>
#include <cstdint>

#define HID 256
#define FEA 192
#define NMAX 50000
#define MB 64           // nodes per block (node kernel)
#define NT 256          // threads per block (node kernel)

#define ACT_STR 260     // act row stride in floats
// smem layout (bytes)
#define SM_W    (MB * ACT_STR * 4)        // 66560 : weight chunk buffers
#define CHUNK_B 9216                      // one term, one buffer: 192 rows * 24 halfs * 2B
#define SM_BIAS (SM_W + 4 * CHUNK_B)      // 103424
#define SM_TOT  (SM_BIAS + 5 * FEA * 4)   // 107264  -> 2 CTAs/SM

__device__ float g_xn[(size_t)NMAX * HID];
__device__ int   g_idx_is64;
// pre-split weights, chunked layout: [chunk16][n(192)][kk(16)]
#define W_ELEMS (HID * FEA + 3 * FEA * FEA)   // 159744
__device__ __align__(16) __nv_bfloat16 g_wh[W_ELEMS];
__device__ __align__(16) __nv_bfloat16 g_wl[W_ELEMS];
#define L0_OFF 0
#define L_OFF(l) (HID * FEA + ((l) - 1) * FEA * FEA)

// ---------------------------------------------------------------------------
// helpers
// ---------------------------------------------------------------------------
__device__ __forceinline__ void split1(float v, uint16_t& h, uint16_t& l) {
    __nv_bfloat16 hb = __float2bfloat16(v);
    float r = v - __bfloat162float(hb);
    __nv_bfloat16 lb = __float2bfloat16(r);
    h = __bfloat16_as_ushort(hb);
    l = __bfloat16_as_ushort(lb);
}
__device__ __forceinline__ void split2(float a, float b, uint32_t& hw, uint32_t& lw) {
    uint16_t ha, la, hb, lb;
    split1(a, ha, la);
    split1(b, hb, lb);
    hw = ((uint32_t)hb << 16) | ha;
    lw = ((uint32_t)lb << 16) | la;
}
__device__ __forceinline__ void mma_bf16(float* d,
                                         uint32_t a0, uint32_t a1, uint32_t a2, uint32_t a3,
                                         uint32_t b0, uint32_t b1) {
    asm volatile(
        "mma.sync.aligned.m16n8k16.row.col.f32.bf16.bf16.f32 "
        "{%0,%1,%2,%3}, {%4,%5,%6,%7}, {%8,%9}, {%0,%1,%2,%3};"
        : "+f"(d[0]), "+f"(d[1]), "+f"(d[2]), "+f"(d[3])
        : "r"(a0), "r"(a1), "r"(a2), "r"(a3), "r"(b0), "r"(b1));
}
__device__ __forceinline__ uint32_t smem_to_u32(const void* p) {
    uint32_t a;
    asm("{ .reg .u64 t; cvta.to.shared.u64 t, %1; cvt.u32.u64 %0, t; }"
        : "=r"(a) : "l"(p));
    return a;
}

// ---------------------------------------------------------------------------
// prep: split all weights to bf16 hi/lo, chunked layout
// ---------------------------------------------------------------------------
__global__ void prep_kernel(const float* __restrict__ W_up,
                            const float* __restrict__ W_lins) {
    int t = blockIdx.x * blockDim.x + threadIdx.x;
    if (t >= W_ELEMS) return;
    int base, el;
    const float* src;
    if (t < HID * FEA) { base = L0_OFF; el = t; src = W_up; }
    else {
        int t2 = t - HID * FEA;
        int l = t2 / (FEA * FEA);
        base = L_OFF(l + 1);
        el = t2 - l * FEA * FEA;
        src = W_lins + l * FEA * FEA;
    }
    int kf = el / FEA, n = el - kf * FEA;
    uint16_t h, l16;
    split1(src[kf * FEA + n], h, l16);
    int dst = base + (kf >> 4) * (16 * FEA) + n * 16 + (kf & 15);
    g_wh[dst] = __ushort_as_bfloat16(h);
    g_wl[dst] = __ushort_as_bfloat16(l16);
}

// ---------------------------------------------------------------------------
// edge stage
// ---------------------------------------------------------------------------
__global__ void detect_idx_kernel(const unsigned int* __restrict__ w, int E) {
    __shared__ int bad;
    if (threadIdx.x == 0) bad = 0;
    __syncthreads();
    int n = E < 512 ? E : 512;
    for (int k = threadIdx.x; k < n; k += blockDim.x)
        if (w[2 * k + 1] != 0u) bad = 1;
    __syncthreads();
    if (threadIdx.x == 0) g_idx_is64 = !bad;
}

__global__ void zero_xn_kernel(int n4) {
    float4* p = reinterpret_cast<float4*>(g_xn);
    const float4 z = make_float4(0.f, 0.f, 0.f, 0.f);
    for (int i = blockIdx.x * blockDim.x + threadIdx.x; i < n4;
         i += gridDim.x * blockDim.x)
        p[i] = z;
}

__global__ __launch_bounds__(256) void edge_kernel(
    const float* __restrict__ x, const float* __restrict__ rbf,
    const void* __restrict__ idx, const float* __restrict__ W_rbf, int E)
{
    const int tid = threadIdx.x;
    const int q   = tid & 63;
    const int eo  = tid >> 6;

    float4 w[6];
#pragma unroll
    for (int r = 0; r < 6; r++)
        w[r] = *reinterpret_cast<const float4*>(W_rbf + r * HID + q * 4);

    const int is64 = g_idx_is64;
    const long long P = ((long long)E + 1) / 2;
    const long long pstep = (long long)gridDim.x * 4;

    for (long long p = (long long)blockIdx.x * 4 + eo; p < P; p += pstep) {
        const long long e0 = 2 * p, e1 = 2 * p + 1;
        const bool has1 = e1 < E;

        const float* rb = rbf + e0 * 6;
        float r00 = rb[0], r01 = rb[1], r02 = rb[2], r03 = rb[3], r04 = rb[4], r05 = rb[5];
        float r10 = 0, r11 = 0, r12 = 0, r13 = 0, r14 = 0, r15 = 0;
        if (has1) { r10 = rb[6]; r11 = rb[7]; r12 = rb[8]; r13 = rb[9]; r14 = rb[10]; r15 = rb[11]; }

        int n0, n1 = 0;
        if (is64) {
            const long long* ip = reinterpret_cast<const long long*>(idx);
            n0 = (int)ip[e0];
            if (has1) n1 = (int)ip[e1];
        } else {
            const int* ip = reinterpret_cast<const int*>(idx);
            n0 = ip[e0];
            if (has1) n1 = ip[e1];
        }

        float4 x0 = *reinterpret_cast<const float4*>(x + e0 * HID + q * 4);
        float4 x1 = make_float4(0, 0, 0, 0);
        if (has1) x1 = *reinterpret_cast<const float4*>(x + e1 * HID + q * 4);

        float4 g0, g1;
        g0.x = r00*w[0].x + r01*w[1].x + r02*w[2].x + r03*w[3].x + r04*w[4].x + r05*w[5].x;
        g0.y = r00*w[0].y + r01*w[1].y + r02*w[2].y + r03*w[3].y + r04*w[4].y + r05*w[5].y;
        g0.z = r00*w[0].z + r01*w[1].z + r02*w[2].z + r03*w[3].z + r04*w[4].z + r05*w[5].z;
        g0.w = r00*w[0].w + r01*w[1].w + r02*w[2].w + r03*w[3].w + r04*w[4].w + r05*w[5].w;
        g1.x = r10*w[0].x + r11*w[1].x + r12*w[2].x + r13*w[3].x + r14*w[4].x + r15*w[5].x;
        g1.y = r10*w[0].y + r11*w[1].y + r12*w[2].y + r13*w[3].y + r14*w[4].y + r15*w[5].y;
        g1.z = r10*w[0].z + r11*w[1].z + r12*w[2].z + r13*w[3].z + r14*w[4].z + r15*w[5].z;
        g1.w = r10*w[0].w + r11*w[1].w + r12*w[2].w + r13*w[3].w + r14*w[4].w + r15*w[5].w;

        float* p0 = g_xn + (size_t)n0 * HID + q * 4;
        asm volatile("red.global.add.v4.f32 [%0], {%1, %2, %3, %4};"
                     :: "l"(p0), "f"(g0.x*x0.x), "f"(g0.y*x0.y), "f"(g0.z*x0.z), "f"(g0.w*x0.w) : "memory");
        if (has1) {
            float* p1 = g_xn + (size_t)n1 * HID + q * 4;
            asm volatile("red.global.add.v4.f32 [%0], {%1, %2, %3, %4};"
                         :: "l"(p1), "f"(g1.x*x1.x), "f"(g1.y*x1.y), "f"(g1.z*x1.z), "f"(g1.w*x1.w) : "memory");
        }
    }
}

// ---------------------------------------------------------------------------
// node MLP: mma.sync bf16 3-term split, precomputed weights, cp.async pipeline
// ---------------------------------------------------------------------------
__device__ __forceinline__ void stage_chunk(
    const __nv_bfloat16* __restrict__ Wh, const __nv_bfloat16* __restrict__ Wl,
    int s, int buf, uint32_t smem_u32, int tid)
{
    const char* srcH = reinterpret_cast<const char*>(Wh + s * 16 * FEA);
    const char* srcL = reinterpret_cast<const char*>(Wl + s * 16 * FEA);
#pragma unroll
    for (int it = 0; it < 3; it++) {
        int t = tid + it * NT;                // 0..767
        int term = t >= 384;
        int u = term ? t - 384 : t;           // 0..383
        int n = u >> 1, seg = u & 1;
        const char* src = (term ? srcL : srcH) + n * 32 + seg * 16;
        uint32_t dst = smem_u32 + SM_W + term * (2 * CHUNK_B) + buf * CHUNK_B
                     + n * 48 + seg * 16;
        asm volatile("cp.async.cg.shared.global [%0], [%1], 16;"
                     :: "r"(dst), "l"(src));
    }
    asm volatile("cp.async.commit_group;");
}

template<int K, bool ACT>
__device__ __forceinline__ void layer(
    const __nv_bfloat16* __restrict__ Wh, const __nv_bfloat16* __restrict__ Wl,
    const float* __restrict__ bias, float* __restrict__ act,
    char* smem, uint32_t smem_u32,
    int tid, int g, int q, int warp_m, int warp_n)
{
    constexpr int S = K / 16;
    float d[12][4];
#pragma unroll
    for (int j = 0; j < 12; j++)
#pragma unroll
        for (int u = 0; u < 4; u++) d[j][u] = 0.f;

    stage_chunk(Wh, Wl, 0, 0, smem_u32, tid);

    const int r0 = warp_m * 16 + g;
#pragma unroll 2
    for (int s = 0; s < S; s++) {
        const int b = s & 1;
        if (s + 1 < S) {
            stage_chunk(Wh, Wl, s + 1, b ^ 1, smem_u32, tid);
            asm volatile("cp.async.wait_group 1;");
        } else {
            asm volatile("cp.async.wait_group 0;");
        }
        __syncthreads();

        // A fragments (fp32 -> bf16 hi/lo)
        const float* p0 = act + r0 * ACT_STR + s * 16 + q * 2;
        const float* p1 = p0 + 8 * ACT_STR;
        float2 v0 = *(const float2*)p0;
        float2 v1 = *(const float2*)p1;
        float2 v2 = *(const float2*)(p0 + 8);
        float2 v3 = *(const float2*)(p1 + 8);
        uint32_t ah[4], al[4];
        split2(v0.x, v0.y, ah[0], al[0]);
        split2(v1.x, v1.y, ah[1], al[1]);
        split2(v2.x, v2.y, ah[2], al[2]);
        split2(v3.x, v3.y, ah[3], al[3]);

        const uint32_t* bhp = reinterpret_cast<const uint32_t*>(smem + SM_W + b * CHUNK_B);
        const uint32_t* blp = reinterpret_cast<const uint32_t*>(smem + SM_W + 2 * CHUNK_B + b * CHUNK_B);
#pragma unroll
        for (int j = 0; j < 12; j++) {
            int n = warp_n * 96 + j * 8 + g;
            uint32_t bh0 = bhp[n * 12 + q],     bh1 = bhp[n * 12 + 4 + q];
            uint32_t bl0 = blp[n * 12 + q],     bl1 = blp[n * 12 + 4 + q];
            mma_bf16(d[j], ah[0], ah[1], ah[2], ah[3], bh0, bh1);
            mma_bf16(d[j], al[0], al[1], al[2], al[3], bh0, bh1);
            mma_bf16(d[j], ah[0], ah[1], ah[2], ah[3], bl0, bl1);
        }
        __syncthreads();
    }

    // epilogue: bias (+silu), write back into act
#pragma unroll
    for (int j = 0; j < 12; j++) {
        int c = warp_n * 96 + j * 8 + q * 2;
        float b0 = bias[c], b1 = bias[c + 1];
        float x0 = d[j][0] + b0, x1 = d[j][1] + b1;
        float x2 = d[j][2] + b0, x3 = d[j][3] + b1;
        if (ACT) {
            x0 = x0 / (1.f + __expf(-x0));
            x1 = x1 / (1.f + __expf(-x1));
            x2 = x2 / (1.f + __expf(-x2));
            x3 = x3 / (1.f + __expf(-x3));
        }
        *(float2*)(act + r0 * ACT_STR + c)       = make_float2(x0, x1);
        *(float2*)(act + (r0 + 8) * ACT_STR + c) = make_float2(x2, x3);
    }
    __syncthreads();
}

__global__ __launch_bounds__(NT, 2) void node_kernel(
    const float* __restrict__ b_up, const float* __restrict__ b_lins,
    const float* __restrict__ W_out, float* __restrict__ out, int N)
{
    extern __shared__ char smem[];
    float* act   = reinterpret_cast<float*>(smem);
    float* sBias = reinterpret_cast<float*>(smem + SM_BIAS);
    const uint32_t smem_u32 = smem_to_u32(smem);

    const int tid = threadIdx.x;
    const int lane = tid & 31, warp = tid >> 5;
    const int g = lane >> 2, q = lane & 3;
    const int warp_m = warp & 3, warp_n = warp >> 2;
    const int node0 = blockIdx.x * MB;

    for (int t = tid; t < FEA; t += NT) {
        sBias[t]           = b_up[t];
        sBias[FEA + t]     = b_lins[t];
        sBias[2 * FEA + t] = b_lins[FEA + t];
        sBias[3 * FEA + t] = b_lins[2 * FEA + t];
        sBias[4 * FEA + t] = W_out[t];
    }
    // load xn tile [64][256]
    for (int t = tid; t < MB * HID / 4; t += NT) {
        int row = t >> 6;
        int c4  = t & 63;
        int node = node0 + row;
        float4 v = (node < N)
            ? reinterpret_cast<const float4*>(g_xn + (size_t)node * HID)[c4]
            : make_float4(0.f, 0.f, 0.f, 0.f);
        *(float4*)(act + row * ACT_STR + c4 * 4) = v;
    }
    __syncthreads();

    layer<HID, false>(g_wh + L0_OFF,   g_wl + L0_OFF,   sBias,           act, smem, smem_u32, tid, g, q, warp_m, warp_n);
    layer<FEA, true >(g_wh + L_OFF(1), g_wl + L_OFF(1), sBias + FEA,     act, smem, smem_u32, tid, g, q, warp_m, warp_n);
    layer<FEA, true >(g_wh + L_OFF(2), g_wl + L_OFF(2), sBias + 2 * FEA, act, smem, smem_u32, tid, g, q, warp_m, warp_n);
    layer<FEA, true >(g_wh + L_OFF(3), g_wl + L_OFF(3), sBias + 3 * FEA, act, smem, smem_u32, tid, g, q, warp_m, warp_n);

    // final projection FEA -> 1 : 4 threads per node
    {
        const int node = tid >> 2, part = tid & 3;
        const float4* hrow = reinterpret_cast<const float4*>(act + node * ACT_STR + part * 48);
        const float4* wv   = reinterpret_cast<const float4*>(sBias + 4 * FEA + part * 48);
        float s = 0.f;
#pragma unroll
        for (int c = 0; c < 12; c++) {
            float4 a = hrow[c], b = wv[c];
            s += a.x * b.x + a.y * b.y + a.z * b.z + a.w * b.w;
        }
        s += __shfl_xor_sync(0xffffffffu, s, 1);
        s += __shfl_xor_sync(0xffffffffu, s, 2);
        if (part == 0 && node0 + node < N) out[node0 + node] = s;
    }
}

// ---------------------------------------------------------------------------
// launch
// ---------------------------------------------------------------------------
extern "C" void kernel_launch(void* const* d_in, const int* in_sizes, int n_in,
                              void* d_out, int out_size)
{
    const float* x    = (const float*)d_in[0];
    const float* rbf  = (const float*)d_in[1];
    const void*  idx  = d_in[2];
    const int wo = (n_in >= 10) ? 4 : 3;
    const float* W_rbf  = (const float*)d_in[wo + 0];
    const float* W_up   = (const float*)d_in[wo + 1];
    const float* b_up   = (const float*)d_in[wo + 2];
    const float* W_lins = (const float*)d_in[wo + 3];
    const float* b_lins = (const float*)d_in[wo + 4];
    const float* W_out  = (const float*)d_in[wo + 5];

    const int E = in_sizes[0] / HID;
    const int N = out_size;

    cudaFuncSetAttribute(node_kernel,
                         cudaFuncAttributeMaxDynamicSharedMemorySize, SM_TOT);

    detect_idx_kernel<<<1, 256>>>((const unsigned int*)idx, E);
    prep_kernel<<<(W_ELEMS + 255) / 256, 256>>>(W_up, W_lins);
    zero_xn_kernel<<<2048, 256>>>(N * HID / 4);
    edge_kernel<<<2048, 256>>>(x, rbf, idx, W_rbf, E);
    node_kernel<<<(N + MB - 1) / MB, NT, SM_TOT>>>(
        b_up, b_lins, W_out, (float*)d_out, N);
}

// round 5
// speedup vs baseline: 1.9813x; 1.0043x over previous
#include <cuda_runtime.h>
#include <cuda_bf16.h>
#include <cstdint>

#define HID 256
#define FEA 192
#define NMAX 50000
#define EMAX 800000
#define MB 64           // nodes per block (node kernel)
#define NT 256          // threads per block (node kernel)

#define ACT_STR 260     // act row stride in floats
// smem layout (bytes)
#define SM_W    (MB * ACT_STR * 4)        // 66560 : weight chunk buffers
#define CHUNK_B 9216                      // one term, one buffer
#define SM_BIAS (SM_W + 4 * CHUNK_B)      // 103424
#define SM_TOT  (SM_BIAS + 5 * FEA * 4)   // 107264  -> 2 CTAs/SM

__device__ float g_xn[(size_t)NMAX * HID];
__device__ int   g_idx_is64;
// CSR sort structures
__device__ int g_cnt[NMAX];
__device__ int g_off[NMAX + 1];
__device__ int g_cur[NMAX];
__device__ int g_sorted[EMAX];
// pre-split weights, chunked layout: [chunk16][n(192)][kk(16)]
#define W_ELEMS (HID * FEA + 3 * FEA * FEA)
__device__ __align__(16) __nv_bfloat16 g_wh[W_ELEMS];
__device__ __align__(16) __nv_bfloat16 g_wl[W_ELEMS];
#define L0_OFF 0
#define L_OFF(l) (HID * FEA + ((l) - 1) * FEA * FEA)

// ---------------------------------------------------------------------------
// helpers
// ---------------------------------------------------------------------------
__device__ __forceinline__ void split1(float v, uint16_t& h, uint16_t& l) {
    __nv_bfloat16 hb = __float2bfloat16(v);
    float r = v - __bfloat162float(hb);
    __nv_bfloat16 lb = __float2bfloat16(r);
    h = __bfloat16_as_ushort(hb);
    l = __bfloat16_as_ushort(lb);
}
__device__ __forceinline__ void split2(float a, float b, uint32_t& hw, uint32_t& lw) {
    uint16_t ha, la, hb, lb;
    split1(a, ha, la);
    split1(b, hb, lb);
    hw = ((uint32_t)hb << 16) | ha;
    lw = ((uint32_t)lb << 16) | la;
}
__device__ __forceinline__ void mma_bf16(float* d,
                                         uint32_t a0, uint32_t a1, uint32_t a2, uint32_t a3,
                                         uint32_t b0, uint32_t b1) {
    asm volatile(
        "mma.sync.aligned.m16n8k16.row.col.f32.bf16.bf16.f32 "
        "{%0,%1,%2,%3}, {%4,%5,%6,%7}, {%8,%9}, {%0,%1,%2,%3};"
        : "+f"(d[0]), "+f"(d[1]), "+f"(d[2]), "+f"(d[3])
        : "r"(a0), "r"(a1), "r"(a2), "r"(a3), "r"(b0), "r"(b1));
}
__device__ __forceinline__ uint32_t smem_to_u32(const void* p) {
    uint32_t a;
    asm("{ .reg .u64 t; cvta.to.shared.u64 t, %1; cvt.u32.u64 %0, t; }"
        : "=r"(a) : "l"(p));
    return a;
}
__device__ __forceinline__ int load_idx(const void* idx, int e, int is64) {
    return is64 ? (int)reinterpret_cast<const long long*>(idx)[e]
                : reinterpret_cast<const int*>(idx)[e];
}

// ---------------------------------------------------------------------------
// prep: split all weights to bf16 hi/lo, chunked layout
// ---------------------------------------------------------------------------
__global__ void prep_kernel(const float* __restrict__ W_up,
                            const float* __restrict__ W_lins) {
    int t = blockIdx.x * blockDim.x + threadIdx.x;
    if (t >= W_ELEMS) return;
    int base, el;
    const float* src;
    if (t < HID * FEA) { base = L0_OFF; el = t; src = W_up; }
    else {
        int t2 = t - HID * FEA;
        int l = t2 / (FEA * FEA);
        base = L_OFF(l + 1);
        el = t2 - l * FEA * FEA;
        src = W_lins + l * FEA * FEA;
    }
    int kf = el / FEA, n = el - kf * FEA;
    uint16_t h, l16;
    split1(src[kf * FEA + n], h, l16);
    int dst = base + (kf >> 4) * (16 * FEA) + n * 16 + (kf & 15);
    g_wh[dst] = __ushort_as_bfloat16(h);
    g_wl[dst] = __ushort_as_bfloat16(l16);
}

// ---------------------------------------------------------------------------
// edge stage: counting-sort by destination node, then gather-reduce
// ---------------------------------------------------------------------------
__global__ void detect_idx_kernel(const unsigned int* __restrict__ w, int E) {
    __shared__ int bad;
    if (threadIdx.x == 0) bad = 0;
    __syncthreads();
    int n = E < 512 ? E : 512;
    for (int k = threadIdx.x; k < n; k += blockDim.x)
        if (w[2 * k + 1] != 0u) bad = 1;
    __syncthreads();
    if (threadIdx.x == 0) g_idx_is64 = !bad;
}

__global__ void zero_cnt_kernel(int N) {
    int t = blockIdx.x * blockDim.x + threadIdx.x;
    if (t < N) g_cnt[t] = 0;
}

__global__ void hist_kernel(const void* __restrict__ idx, int E) {
    int e = blockIdx.x * blockDim.x + threadIdx.x;
    if (e >= E) return;
    atomicAdd(&g_cnt[load_idx(idx, e, g_idx_is64)], 1);
}

__global__ __launch_bounds__(1024) void scan_kernel(int N) {
    __shared__ int part[1024];
    const int tid = threadIdx.x;
    const int chunk = (N + 1023) / 1024;
    const int base = tid * chunk;
    int s = 0;
    for (int k = 0; k < chunk; k++) {
        int i = base + k;
        if (i < N) s += g_cnt[i];
    }
    part[tid] = s;
    __syncthreads();
    for (int d = 1; d < 1024; d <<= 1) {
        int v = (tid >= d) ? part[tid - d] : 0;
        __syncthreads();
        part[tid] += v;
        __syncthreads();
    }
    int run = part[tid] - s;   // exclusive prefix for this chunk
    for (int k = 0; k < chunk; k++) {
        int i = base + k;
        if (i < N) {
            g_off[i] = run;
            g_cur[i] = run;
            run += g_cnt[i];
        }
    }
    if (tid == 1023) g_off[N] = part[1023];
}

__global__ void scatter_kernel(const void* __restrict__ idx, int E) {
    int e = blockIdx.x * blockDim.x + threadIdx.x;
    if (e >= E) return;
    int n = load_idx(idx, e, g_idx_is64);
    int p = atomicAdd(&g_cur[n], 1);
    g_sorted[p] = e;
}

// one warp per node: gather its edges, fused rbf-gate, register accumulate
__global__ __launch_bounds__(256) void gather_kernel(
    const float* __restrict__ x, const float* __restrict__ rbf,
    const float* __restrict__ W_rbf, int N)
{
    const int warp = (blockIdx.x * blockDim.x + threadIdx.x) >> 5;
    const int lane = threadIdx.x & 31;
    if (warp >= N) return;

    float4 wa[6], wb[6];
#pragma unroll
    for (int r = 0; r < 6; r++) {
        wa[r] = *reinterpret_cast<const float4*>(W_rbf + r * HID + lane * 8);
        wb[r] = *reinterpret_cast<const float4*>(W_rbf + r * HID + lane * 8 + 4);
    }

    const int start = g_off[warp], end = g_off[warp + 1];
    float4 accA = make_float4(0.f, 0.f, 0.f, 0.f), accB = accA;

    int k = start;
    for (; k + 2 <= end; k += 2) {
        int e0 = g_sorted[k], e1 = g_sorted[k + 1];
        const float* rb0 = rbf + (size_t)e0 * 6;
        const float* rb1 = rbf + (size_t)e1 * 6;
        float2 p01 = *(const float2*)rb0, p23 = *(const float2*)(rb0 + 2), p45 = *(const float2*)(rb0 + 4);
        float2 q01 = *(const float2*)rb1, q23 = *(const float2*)(rb1 + 2), q45 = *(const float2*)(rb1 + 4);
        const float* xp0 = x + (size_t)e0 * HID + lane * 8;
        const float* xp1 = x + (size_t)e1 * HID + lane * 8;
        float4 xa0 = *(const float4*)xp0, xb0 = *(const float4*)(xp0 + 4);
        float4 xa1 = *(const float4*)xp1, xb1 = *(const float4*)(xp1 + 4);

        float4 g;
        g.x = p01.x*wa[0].x + p01.y*wa[1].x + p23.x*wa[2].x + p23.y*wa[3].x + p45.x*wa[4].x + p45.y*wa[5].x;
        g.y = p01.x*wa[0].y + p01.y*wa[1].y + p23.x*wa[2].y + p23.y*wa[3].y + p45.x*wa[4].y + p45.y*wa[5].y;
        g.z = p01.x*wa[0].z + p01.y*wa[1].z + p23.x*wa[2].z + p23.y*wa[3].z + p45.x*wa[4].z + p45.y*wa[5].z;
        g.w = p01.x*wa[0].w + p01.y*wa[1].w + p23.x*wa[2].w + p23.y*wa[3].w + p45.x*wa[4].w + p45.y*wa[5].w;
        accA.x += g.x*xa0.x; accA.y += g.y*xa0.y; accA.z += g.z*xa0.z; accA.w += g.w*xa0.w;
        g.x = p01.x*wb[0].x + p01.y*wb[1].x + p23.x*wb[2].x + p23.y*wb[3].x + p45.x*wb[4].x + p45.y*wb[5].x;
        g.y = p01.x*wb[0].y + p01.y*wb[1].y + p23.x*wb[2].y + p23.y*wb[3].y + p45.x*wb[4].y + p45.y*wb[5].y;
        g.z = p01.x*wb[0].z + p01.y*wb[1].z + p23.x*wb[2].z + p23.y*wb[3].z + p45.x*wb[4].z + p45.y*wb[5].z;
        g.w = p01.x*wb[0].w + p01.y*wb[1].w + p23.x*wb[2].w + p23.y*wb[3].w + p45.x*wb[4].w + p45.y*wb[5].w;
        accB.x += g.x*xb0.x; accB.y += g.y*xb0.y; accB.z += g.z*xb0.z; accB.w += g.w*xb0.w;

        g.x = q01.x*wa[0].x + q01.y*wa[1].x + q23.x*wa[2].x + q23.y*wa[3].x + q45.x*wa[4].x + q45.y*wa[5].x;
        g.y = q01.x*wa[0].y + q01.y*wa[1].y + q23.x*wa[2].y + q23.y*wa[3].y + q45.x*wa[4].y + q45.y*wa[5].y;
        g.z = q01.x*wa[0].z + q01.y*wa[1].z + q23.x*wa[2].z + q23.y*wa[3].z + q45.x*wa[4].z + q45.y*wa[5].z;
        g.w = q01.x*wa[0].w + q01.y*wa[1].w + q23.x*wa[2].w + q23.y*wa[3].w + q45.x*wa[4].w + q45.y*wa[5].w;
        accA.x += g.x*xa1.x; accA.y += g.y*xa1.y; accA.z += g.z*xa1.z; accA.w += g.w*xa1.w;
        g.x = q01.x*wb[0].x + q01.y*wb[1].x + q23.x*wb[2].x + q23.y*wb[3].x + q45.x*wb[4].x + q45.y*wb[5].x;
        g.y = q01.x*wb[0].y + q01.y*wb[1].y + q23.x*wb[2].y + q23.y*wb[3].y + q45.x*wb[4].y + q45.y*wb[5].y;
        g.z = q01.x*wb[0].z + q01.y*wb[1].z + q23.x*wb[2].z + q23.y*wb[3].z + q45.x*wb[4].z + q45.y*wb[5].z;
        g.w = q01.x*wb[0].w + q01.y*wb[1].w + q23.x*wb[2].w + q23.y*wb[3].w + q45.x*wb[4].w + q45.y*wb[5].w;
        accB.x += g.x*xb1.x; accB.y += g.y*xb1.y; accB.z += g.z*xb1.z; accB.w += g.w*xb1.w;
    }
    if (k < end) {
        int e0 = g_sorted[k];
        const float* rb0 = rbf + (size_t)e0 * 6;
        float2 p01 = *(const float2*)rb0, p23 = *(const float2*)(rb0 + 2), p45 = *(const float2*)(rb0 + 4);
        const float* xp0 = x + (size_t)e0 * HID + lane * 8;
        float4 xa0 = *(const float4*)xp0, xb0 = *(const float4*)(xp0 + 4);
        float4 g;
        g.x = p01.x*wa[0].x + p01.y*wa[1].x + p23.x*wa[2].x + p23.y*wa[3].x + p45.x*wa[4].x + p45.y*wa[5].x;
        g.y = p01.x*wa[0].y + p01.y*wa[1].y + p23.x*wa[2].y + p23.y*wa[3].y + p45.x*wa[4].y + p45.y*wa[5].y;
        g.z = p01.x*wa[0].z + p01.y*wa[1].z + p23.x*wa[2].z + p23.y*wa[3].z + p45.x*wa[4].z + p45.y*wa[5].z;
        g.w = p01.x*wa[0].w + p01.y*wa[1].w + p23.x*wa[2].w + p23.y*wa[3].w + p45.x*wa[4].w + p45.y*wa[5].w;
        accA.x += g.x*xa0.x; accA.y += g.y*xa0.y; accA.z += g.z*xa0.z; accA.w += g.w*xa0.w;
        g.x = p01.x*wb[0].x + p01.y*wb[1].x + p23.x*wb[2].x + p23.y*wb[3].x + p45.x*wb[4].x + p45.y*wb[5].x;
        g.y = p01.x*wb[0].y + p01.y*wb[1].y + p23.x*wb[2].y + p23.y*wb[3].y + p45.x*wb[4].y + p45.y*wb[5].y;
        g.z = p01.x*wb[0].z + p01.y*wb[1].z + p23.x*wb[2].z + p23.y*wb[3].z + p45.x*wb[4].z + p45.y*wb[5].z;
        g.w = p01.x*wb[0].w + p01.y*wb[1].w + p23.x*wb[2].w + p23.y*wb[3].w + p45.x*wb[4].w + p45.y*wb[5].w;
        accB.x += g.x*xb0.x; accB.y += g.y*xb0.y; accB.z += g.z*xb0.z; accB.w += g.w*xb0.w;
    }

    float* dst = g_xn + (size_t)warp * HID + lane * 8;
    *reinterpret_cast<float4*>(dst)     = accA;
    *reinterpret_cast<float4*>(dst + 4) = accB;
}

// ---------------------------------------------------------------------------
// node MLP: mma.sync bf16 3-term split, precomputed weights, cp.async pipeline
// ---------------------------------------------------------------------------
__device__ __forceinline__ void stage_chunk(
    const __nv_bfloat16* __restrict__ Wh, const __nv_bfloat16* __restrict__ Wl,
    int s, int buf, uint32_t smem_u32, int tid)
{
    const char* srcH = reinterpret_cast<const char*>(Wh + s * 16 * FEA);
    const char* srcL = reinterpret_cast<const char*>(Wl + s * 16 * FEA);
#pragma unroll
    for (int it = 0; it < 3; it++) {
        int t = tid + it * NT;
        int term = t >= 384;
        int u = term ? t - 384 : t;
        int n = u >> 1, seg = u & 1;
        const char* src = (term ? srcL : srcH) + n * 32 + seg * 16;
        uint32_t dst = smem_u32 + SM_W + term * (2 * CHUNK_B) + buf * CHUNK_B
                     + n * 48 + seg * 16;
        asm volatile("cp.async.cg.shared.global [%0], [%1], 16;"
                     :: "r"(dst), "l"(src));
    }
    asm volatile("cp.async.commit_group;");
}

template<int K, bool ACT>
__device__ __forceinline__ void layer(
    const __nv_bfloat16* __restrict__ Wh, const __nv_bfloat16* __restrict__ Wl,
    const float* __restrict__ bias, float* __restrict__ act,
    char* smem, uint32_t smem_u32,
    int tid, int g, int q, int warp_m, int warp_n)
{
    constexpr int S = K / 16;
    float d[12][4];
#pragma unroll
    for (int j = 0; j < 12; j++)
#pragma unroll
        for (int u = 0; u < 4; u++) d[j][u] = 0.f;

    stage_chunk(Wh, Wl, 0, 0, smem_u32, tid);

    const int r0 = warp_m * 16 + g;
#pragma unroll 2
    for (int s = 0; s < S; s++) {
        const int b = s & 1;
        if (s + 1 < S) {
            stage_chunk(Wh, Wl, s + 1, b ^ 1, smem_u32, tid);
            asm volatile("cp.async.wait_group 1;");
        } else {
            asm volatile("cp.async.wait_group 0;");
        }
        __syncthreads();

        const float* p0 = act + r0 * ACT_STR + s * 16 + q * 2;
        const float* p1 = p0 + 8 * ACT_STR;
        float2 v0 = *(const float2*)p0;
        float2 v1 = *(const float2*)p1;
        float2 v2 = *(const float2*)(p0 + 8);
        float2 v3 = *(const float2*)(p1 + 8);
        uint32_t ah[4], al[4];
        split2(v0.x, v0.y, ah[0], al[0]);
        split2(v1.x, v1.y, ah[1], al[1]);
        split2(v2.x, v2.y, ah[2], al[2]);
        split2(v3.x, v3.y, ah[3], al[3]);

        const uint32_t* bhp = reinterpret_cast<const uint32_t*>(smem + SM_W + b * CHUNK_B);
        const uint32_t* blp = reinterpret_cast<const uint32_t*>(smem + SM_W + 2 * CHUNK_B + b * CHUNK_B);
#pragma unroll
        for (int j = 0; j < 12; j++) {
            int n = warp_n * 96 + j * 8 + g;
            uint32_t bh0 = bhp[n * 12 + q],     bh1 = bhp[n * 12 + 4 + q];
            uint32_t bl0 = blp[n * 12 + q],     bl1 = blp[n * 12 + 4 + q];
            mma_bf16(d[j], ah[0], ah[1], ah[2], ah[3], bh0, bh1);
            mma_bf16(d[j], al[0], al[1], al[2], al[3], bh0, bh1);
            mma_bf16(d[j], ah[0], ah[1], ah[2], ah[3], bl0, bl1);
        }
        __syncthreads();
    }

#pragma unroll
    for (int j = 0; j < 12; j++) {
        int c = warp_n * 96 + j * 8 + q * 2;
        float b0 = bias[c], b1 = bias[c + 1];
        float x0 = d[j][0] + b0, x1 = d[j][1] + b1;
        float x2 = d[j][2] + b0, x3 = d[j][3] + b1;
        if (ACT) {
            x0 = x0 / (1.f + __expf(-x0));
            x1 = x1 / (1.f + __expf(-x1));
            x2 = x2 / (1.f + __expf(-x2));
            x3 = x3 / (1.f + __expf(-x3));
        }
        *(float2*)(act + r0 * ACT_STR + c)       = make_float2(x0, x1);
        *(float2*)(act + (r0 + 8) * ACT_STR + c) = make_float2(x2, x3);
    }
    __syncthreads();
}

__global__ __launch_bounds__(NT, 2) void node_kernel(
    const float* __restrict__ b_up, const float* __restrict__ b_lins,
    const float* __restrict__ W_out, float* __restrict__ out, int N)
{
    extern __shared__ char smem[];
    float* act   = reinterpret_cast<float*>(smem);
    float* sBias = reinterpret_cast<float*>(smem + SM_BIAS);
    const uint32_t smem_u32 = smem_to_u32(smem);

    const int tid = threadIdx.x;
    const int lane = tid & 31, warp = tid >> 5;
    const int g = lane >> 2, q = lane & 3;
    const int warp_m = warp & 3, warp_n = warp >> 2;
    const int node0 = blockIdx.x * MB;

    for (int t = tid; t < FEA; t += NT) {
        sBias[t]           = b_up[t];
        sBias[FEA + t]     = b_lins[t];
        sBias[2 * FEA + t] = b_lins[FEA + t];
        sBias[3 * FEA + t] = b_lins[2 * FEA + t];
        sBias[4 * FEA + t] = W_out[t];
    }
    for (int t = tid; t < MB * HID / 4; t += NT) {
        int row = t >> 6;
        int c4  = t & 63;
        int node = node0 + row;
        float4 v = (node < N)
            ? reinterpret_cast<const float4*>(g_xn + (size_t)node * HID)[c4]
            : make_float4(0.f, 0.f, 0.f, 0.f);
        *(float4*)(act + row * ACT_STR + c4 * 4) = v;
    }
    __syncthreads();

    layer<HID, false>(g_wh + L0_OFF,   g_wl + L0_OFF,   sBias,           act, smem, smem_u32, tid, g, q, warp_m, warp_n);
    layer<FEA, true >(g_wh + L_OFF(1), g_wl + L_OFF(1), sBias + FEA,     act, smem, smem_u32, tid, g, q, warp_m, warp_n);
    layer<FEA, true >(g_wh + L_OFF(2), g_wl + L_OFF(2), sBias + 2 * FEA, act, smem, smem_u32, tid, g, q, warp_m, warp_n);
    layer<FEA, true >(g_wh + L_OFF(3), g_wl + L_OFF(3), sBias + 3 * FEA, act, smem, smem_u32, tid, g, q, warp_m, warp_n);

    {
        const int node = tid >> 2, part = tid & 3;
        const float4* hrow = reinterpret_cast<const float4*>(act + node * ACT_STR + part * 48);
        const float4* wv   = reinterpret_cast<const float4*>(sBias + 4 * FEA + part * 48);
        float s = 0.f;
#pragma unroll
        for (int c = 0; c < 12; c++) {
            float4 a = hrow[c], b = wv[c];
            s += a.x * b.x + a.y * b.y + a.z * b.z + a.w * b.w;
        }
        s += __shfl_xor_sync(0xffffffffu, s, 1);
        s += __shfl_xor_sync(0xffffffffu, s, 2);
        if (part == 0 && node0 + node < N) out[node0 + node] = s;
    }
}

// ---------------------------------------------------------------------------
// launch
// ---------------------------------------------------------------------------
extern "C" void kernel_launch(void* const* d_in, const int* in_sizes, int n_in,
                              void* d_out, int out_size)
{
    const float* x    = (const float*)d_in[0];
    const float* rbf  = (const float*)d_in[1];
    const void*  idx  = d_in[2];
    const int wo = (n_in >= 10) ? 4 : 3;
    const float* W_rbf  = (const float*)d_in[wo + 0];
    const float* W_up   = (const float*)d_in[wo + 1];
    const float* b_up   = (const float*)d_in[wo + 2];
    const float* W_lins = (const float*)d_in[wo + 3];
    const float* b_lins = (const float*)d_in[wo + 4];
    const float* W_out  = (const float*)d_in[wo + 5];

    const int E = in_sizes[0] / HID;
    const int N = out_size;

    cudaFuncSetAttribute(node_kernel,
                         cudaFuncAttributeMaxDynamicSharedMemorySize, SM_TOT);

    detect_idx_kernel<<<1, 256>>>((const unsigned int*)idx, E);
    prep_kernel<<<(W_ELEMS + 255) / 256, 256>>>(W_up, W_lins);
    zero_cnt_kernel<<<(N + 255) / 256, 256>>>(N);
    hist_kernel<<<(E + 255) / 256, 256>>>(idx, E);
    scan_kernel<<<1, 1024>>>(N);
    scatter_kernel<<<(E + 255) / 256, 256>>>(idx, E);
    gather_kernel<<<(N * 32 + 255) / 256, 256>>>(x, rbf, W_rbf, N);
    node_kernel<<<(N + MB - 1) / MB, NT, SM_TOT>>>(
        b_up, b_lins, W_out, (float*)d_out, N);
}